// round 17
// baseline (speedup 1.0000x reference)
#include <cuda_runtime.h>
#include <math.h>

#define NN   100000
#define EE   3200000
#define INC  256
#define HIDC 32
#define OUTC 40

// ---------------- scratch (static device globals; no allocation) ----------------
__device__ float g_dinv[NN];          // D^-1/2 (with self-loop)
__device__ int   g_degi[NN];          // incoming-edge counts
__device__ int   g_off [NN];          // CSR row offsets (exclusive)
__device__ int   g_cur [NN];          // fill cursors (== row end after fill)
__device__ int   g_part [128];        // scan partials
__device__ int   g_part2[128];        // scanned partials
__device__ int2  g_csr[EE];           // CSR: {src, weight-bits} packed per slot
__device__ float g_h1  [NN * HIDC];   // x @ W1
__device__ float g_helu[NN * HIDC];   // elu(agg1 + b1)
__device__ float g_y   [NN * HIDC];   // relu(bn(helu))
__device__ float g_bn[64];            // [0:32) sum, [32:64) sumsq
__device__ int   g_is32;              // 1 if edge_index holds int32, 0 if int64

// ---------------- edge-index access (dtype-agnostic) ----------------
__device__ __forceinline__ int eidx(const void* ei, long long pos, int is32) {
    if (is32) return ((const int*)ei)[pos];
    return (int)((const long long*)ei)[pos];
}

__global__ void k_probe(const void* ei) {
    if (threadIdx.x == 0) {
        const unsigned long long* p = (const unsigned long long*)ei;
        int is32 = 0;
        for (int i = 0; i < 64; i++)
            if (p[i] >= (unsigned long long)NN) is32 = 1;
        g_is32 = is32;
    }
}

// ---------------- build kernels ----------------
__global__ void k_init() {
    int i = blockIdx.x * 256 + threadIdx.x;
    if (i < NN) g_degi[i] = 0;
    if (blockIdx.x == 0 && threadIdx.x < 64) g_bn[threadIdx.x] = 0.0f;
}

__global__ void k_deg(const void* __restrict__ ei) {
    int e = blockIdx.x * 256 + threadIdx.x;
    if (e >= EE) return;
    int d = eidx(ei, (long long)EE + e, g_is32);
    if ((unsigned)d < NN) atomicAdd(&g_degi[d], 1);
}

// scan1 also writes g_dinv (folded former k_dinv)
__global__ void k_scan1() {
    __shared__ int s[1024];
    int t = threadIdx.x;
    int i = blockIdx.x * 1024 + t;
    int v = (i < NN) ? g_degi[i] : 0;
    if (i < NN) g_dinv[i] = rsqrtf((float)v + 1.0f);   // +1 self-loop
    s[t] = v;
    __syncthreads();
    for (int o = 1; o < 1024; o <<= 1) {
        int tv = (t >= o) ? s[t - o] : 0;
        __syncthreads();
        s[t] += tv;
        __syncthreads();
    }
    if (i < NN) g_off[i] = s[t] - v;
    if (t == 1023) g_part[blockIdx.x] = s[1023];
}

__global__ void k_scan2(int nblk) {
    __shared__ int s[128];
    int t = threadIdx.x;
    int v = (t < nblk) ? g_part[t] : 0;
    s[t] = v;
    __syncthreads();
    for (int o = 1; o < 128; o <<= 1) {
        int tv = (t >= o) ? s[t - o] : 0;
        __syncthreads();
        s[t] += tv;
        __syncthreads();
    }
    if (t < nblk) g_part2[t] = s[t] - v;
}

__global__ void k_scan3() {
    int i = blockIdx.x * 256 + threadIdx.x;
    if (i < NN) {
        int o = g_off[i] + g_part2[i >> 10];
        g_off[i] = o;
        g_cur[i] = o;
    }
}

// ---------------- fused: CSR fill + GEMM1 (heterogeneous block roles) ----------
// Every 9th block (bid%9==8) is a gemm tile (64 rows, f32x2); the rest fill CSR.
// Both roles depend only on scan3 output; interleaving co-resides memory-bound
// fill blocks with issue-bound gemm blocks on each SM.
#define FILL_BLKS  12500                 // ceil(EE/256)
#define GEMM_TILES 1563                  // ceil(NN/64)
#define FUSED_BLKS 14072                 // gemm count = 1563, fill count = 12509

__global__ void __launch_bounds__(256) k_fill_gemm1(
    const void* __restrict__ ei,
    const float* __restrict__ x, const float* __restrict__ W1) {
    __shared__ __align__(16) float Ws[64 * 32];    // 8 KB  (k-chunk of W1)
    __shared__ __align__(16) float Xs[64][66];     // 16.9 KB (transposed: [k][row])
    const int bid = blockIdx.x;
    const int tid = threadIdx.x;

    if ((bid % 9) != 8) {
        // ---- fill role ----
        int fb = bid - (bid + 1) / 9;              // fill block index 0..12508
        if (fb >= FILL_BLKS) return;
        int e = fb * 256 + tid;
        if (e >= EE) return;
        int is32 = g_is32;
        int s = eidx(ei, e, is32);
        int d = eidx(ei, (long long)EE + e, is32);
        if ((unsigned)s >= NN || (unsigned)d >= NN) return;
        int pos = atomicAdd(&g_cur[d], 1);
        if (pos < EE)
            g_csr[pos] = make_int2(s, __float_as_int(g_dinv[s] * g_dinv[d]));
        return;
    }

    // ---- gemm role: 64 rows, 4 k-chunks of 64, packed f32x2 (2 rows/FFMA) ----
    const int row0 = (bid / 9) * 64;
    const int lane = tid & 31, w = tid >> 5;
    const int pb = w * 4;                          // warp owns row-pairs pb..pb+3

    unsigned long long acc0 = 0ull, acc1 = 0ull, acc2 = 0ull, acc3 = 0ull;

    for (int kc = 0; kc < 4; kc++) {
        for (int i = tid; i < 64 * 32; i += 256)
            Ws[i] = W1[(kc * 64) * 32 + i];
        for (int i = tid; i < 64 * 64; i += 256) {
            int r = i >> 6, k = i & 63;
            int row = row0 + r;
            Xs[k][r] = (row < NN) ? x[(size_t)row * INC + kc * 64 + k] : 0.0f;
        }
        __syncthreads();

        const unsigned long long* Xt2 = (const unsigned long long*)&Xs[0][0];
#pragma unroll 8
        for (int k = 0; k < 64; k++) {
            unsigned int wb = __float_as_uint(Ws[k * 32 + lane]);
            unsigned long long w2;
            asm("mov.b64 %0, {%1, %1};" : "=l"(w2) : "r"(wb));
            unsigned long long xa = Xt2[k * 33 + pb + 0];
            unsigned long long xb = Xt2[k * 33 + pb + 1];
            unsigned long long xc = Xt2[k * 33 + pb + 2];
            unsigned long long xd = Xt2[k * 33 + pb + 3];
            asm("fma.rn.f32x2 %0, %1, %2, %0;" : "+l"(acc0) : "l"(xa), "l"(w2));
            asm("fma.rn.f32x2 %0, %1, %2, %0;" : "+l"(acc1) : "l"(xb), "l"(w2));
            asm("fma.rn.f32x2 %0, %1, %2, %0;" : "+l"(acc2) : "l"(xc), "l"(w2));
            asm("fma.rn.f32x2 %0, %1, %2, %0;" : "+l"(acc3) : "l"(xd), "l"(w2));
        }
        __syncthreads();
    }

    unsigned long long accs[4] = {acc0, acc1, acc2, acc3};
#pragma unroll
    for (int p = 0; p < 4; p++) {
        int r = row0 + (pb + p) * 2;
        if (r < NN)     g_h1[r * HIDC + lane]       = __uint_as_float((unsigned int)accs[p]);
        if (r + 1 < NN) g_h1[(r + 1) * HIDC + lane] = __uint_as_float((unsigned int)(accs[p] >> 32));
    }
}

// ---------------- gather layer 1 (fused +b1, ELU, BN stats) ----------------
__global__ void k_gather1(const float* __restrict__ b1) {
    __shared__ float sbn[64];
    int tid = threadIdx.x;
    if (tid < 64) sbn[tid] = 0.0f;
    __syncthreads();

    int lane = tid & 31;
    int r = blockIdx.x * 8 + (tid >> 5);          // 12500*8 = 100000 exact
    int base = g_off[r];
    int end  = g_cur[r];
    float dv = g_dinv[r];
    float acc = g_h1[r * HIDC + lane] * dv * dv;  // self-loop term

    while (end - base >= 32) {
        int2 v2 = g_csr[base + lane];
#pragma unroll
        for (int i = 0; i < 32; i++) {
            int   si = __shfl_sync(0xffffffffu, v2.x, i);
            float wi = __int_as_float(__shfl_sync(0xffffffffu, v2.y, i));
            acc += g_h1[si * HIDC + lane] * wi;
        }
        base += 32;
    }
    if (base < end) {
        int n = end - base;
        int2 v2 = make_int2(0, 0);
        if (lane < n) v2 = g_csr[base + lane];
        for (int i = 0; i < n; i++) {
            int   si = __shfl_sync(0xffffffffu, v2.x, i);
            float wi = __int_as_float(__shfl_sync(0xffffffffu, v2.y, i));
            acc += g_h1[si * HIDC + lane] * wi;
        }
    }

    float v = acc + b1[lane];
    float h = (v > 0.0f) ? v : expm1f(v);         // ELU
    g_helu[r * HIDC + lane] = h;

    atomicAdd(&sbn[lane],      h);
    atomicAdd(&sbn[32 + lane], h * h);
    __syncthreads();
    if (tid < 64) atomicAdd(&g_bn[tid], sbn[tid]);
}

// ---------------- y = relu(bn(helu)) — each thread derives scale/shift ----------
__global__ void k_bnrelu() {
    int i = blockIdx.x * 256 + threadIdx.x;
    if (i < NN * HIDC) {
        int j = i & 31;
        float mean = g_bn[j] * (1.0f / NN);
        float var  = g_bn[32 + j] * (1.0f / NN) - mean * mean;
        float sc   = rsqrtf(var + 1e-5f);
        float v = (g_helu[i] - mean) * sc;
        g_y[i] = (v > 0.0f) ? v : 0.0f;
    }
}

// ---------------- gather layer 2 on y (32ch), fused W2 GEMM + b2 + log_softmax ----
__global__ void k_gather2(const float* __restrict__ W2, const float* __restrict__ b2,
                          float* __restrict__ out) {
    __shared__ float W2s[HIDC * OUTC];
    __shared__ float b2s[OUTC];
    int tid = threadIdx.x;
    for (int i = tid; i < HIDC * OUTC; i += 256) W2s[i] = W2[i];
    if (tid < OUTC) b2s[tid] = b2[tid];
    __syncthreads();

    int lane = tid & 31;
    int r = blockIdx.x * 8 + (tid >> 5);
    int base = g_off[r];
    int end  = g_cur[r];
    float dv = g_dinv[r];
    float acc = g_y[r * HIDC + lane] * dv * dv;   // self-loop

    while (end - base >= 32) {
        int2 v2 = g_csr[base + lane];
#pragma unroll
        for (int i = 0; i < 32; i++) {
            int   si = __shfl_sync(0xffffffffu, v2.x, i);
            float wi = __int_as_float(__shfl_sync(0xffffffffu, v2.y, i));
            acc += g_y[si * HIDC + lane] * wi;
        }
        base += 32;
    }
    if (base < end) {
        int n = end - base;
        int2 v2 = make_int2(0, 0);
        if (lane < n) v2 = g_csr[base + lane];
        for (int i = 0; i < n; i++) {
            int   si = __shfl_sync(0xffffffffu, v2.x, i);
            float wi = __int_as_float(__shfl_sync(0xffffffffu, v2.y, i));
            acc += g_y[si * HIDC + lane] * wi;
        }
    }

    // out[c] = sum_k aggy[k] * W2[k][c] + b2[c]   (aggy[k] lives in lane k's acc)
    float o0 = b2s[lane];
    float o1 = (lane < 8) ? b2s[32 + lane] : -1e30f;
#pragma unroll
    for (int k = 0; k < HIDC; k++) {
        float yk = __shfl_sync(0xffffffffu, acc, k);
        o0 += yk * W2s[k * OUTC + lane];
        if (lane < 8) o1 += yk * W2s[k * OUTC + 32 + lane];
    }

    float m = fmaxf(o0, o1);
#pragma unroll
    for (int o = 16; o > 0; o >>= 1) m = fmaxf(m, __shfl_xor_sync(0xffffffffu, m, o));
    float s = expf(o0 - m) + ((lane < 8) ? expf(o1 - m) : 0.0f);
#pragma unroll
    for (int o = 16; o > 0; o >>= 1) s += __shfl_xor_sync(0xffffffffu, s, o);
    float lse = logf(s) + m;
    out[r * OUTC + lane] = o0 - lse;
    if (lane < 8) out[r * OUTC + 32 + lane] = o1 - lse;
}

// ---------------- launch ----------------
extern "C" void kernel_launch(void* const* d_in, const int* in_sizes, int n_in,
                              void* d_out, int out_size) {
    const float* x  = (const float*)d_in[0];
    const void*  ei = d_in[1];
    const float* W1 = (const float*)d_in[2];
    const float* b1 = (const float*)d_in[3];
    const float* W2 = (const float*)d_in[4];
    const float* b2 = (const float*)d_in[5];
    for (int i = 0; i < n_in; i++) {
        switch (in_sizes[i]) {
            case NN * INC:     x  = (const float*)d_in[i]; break;
            case 2 * EE:       ei = d_in[i];               break;
            case INC * HIDC:   W1 = (const float*)d_in[i]; break;
            case HIDC:         b1 = (const float*)d_in[i]; break;
            case HIDC * OUTC:  W2 = (const float*)d_in[i]; break;
            case OUTC:         b2 = (const float*)d_in[i]; break;
            default: break;
        }
    }
    float* out = (float*)d_out;

    const int NSCAN = (NN + 1023) / 1024;   // 98

    k_probe     <<<1, 32>>>(ei);
    k_init      <<<(NN + 255) / 256, 256>>>();
    k_deg       <<<(EE + 255) / 256, 256>>>(ei);
    k_scan1     <<<NSCAN, 1024>>>();
    k_scan2     <<<1, 128>>>(NSCAN);
    k_scan3     <<<(NN + 255) / 256, 256>>>();
    k_fill_gemm1<<<FUSED_BLKS, 256>>>(ei, x, W1);
    k_gather1   <<<NN / 8, 256>>>(b1);
    k_bnrelu    <<<(NN * HIDC + 255) / 256, 256>>>();
    k_gather2   <<<NN / 8, 256>>>(W2, b2, out);
}